// round 7
// baseline (speedup 1.0000x reference)
#include <cuda_runtime.h>
#include <cstdint>

#define W_IMG 512
#define H_IMG 512
#define HW    (512*512)
#define NB    4
#define EPS   1e-5f

#define TILE_W 64
#define TILE_H 8
#define BX 32
#define BY 8
#define NTHREADS (BX*BY)
#define PPT 2
#define HALO 2
#define SM_W (TILE_W + 2*HALO)   // 68
#define SM_H (TILE_H + 2*HALO)   // 12

#define NPROD 128                 // gray-max producer blocks (wave-1 resident)
#define CH_PB (NPROD / NB)        // 32 chunks per batch
#define NBLK_MAIN (NB * (H_IMG/TILE_H) * (W_IMG/TILE_W))    // 2048

// scratch (no device allocs) — counters reset by the electing last block each replay
__device__ float g_gmax_partial[NPROD];
__device__ int   g_count;
__device__ int   g_done;
__device__ float g_blockA[NBLK_MAIN];
__device__ float g_blockB[NBLK_MAIN];

// ---- cp.async helpers ----
__device__ __forceinline__ void cp_async8(uint32_t dst_smem, const float* src) {
    asm volatile("cp.async.ca.shared.global [%0], [%1], 8;"
                 :: "r"(dst_smem), "l"(src));
}
__device__ __forceinline__ void cp_commit() {
    asm volatile("cp.async.commit_group;" ::: "memory");
}

__global__ __launch_bounds__(NTHREADS, 4)
void intensity_loss_main(const float* __restrict__ fake,
                         const float* __restrict__ gamma_hdr,
                         const float* __restrict__ hdr_im,
                         const float* __restrict__ r_weights,
                         const float* __restrict__ f_factors,
                         const float* __restrict__ gray,
                         float* __restrict__ out) {
    __shared__ __align__(16) float sf[SM_H * SM_W];
    __shared__ __align__(16) float sg[SM_H * SM_W];
    __shared__ __align__(16) float sh[SM_H * SM_W];
    // weight ring: 3 stages x 5 taps x BY rows x 64 floats (each thread reads only its own slot)
    __shared__ __align__(16) float wbuf[3][5][BY][TILE_W];
    __shared__ float redA[BY], redB[BY];
    __shared__ float s_gmax;
    __shared__ int   s_last;

    const int b     = blockIdx.z;
    const int wbase = blockIdx.x * TILE_W;
    const int hbase = blockIdx.y * TILE_H;
    const int tx    = threadIdx.x;
    const int ty    = threadIdx.y;
    const int tid   = ty * BX + tx;
    const int lbid  = blockIdx.x + (int)gridDim.x * (blockIdx.y + 64 * blockIdx.z);

    const int lw = tx * PPT;
    const int lh = ty;
    const int gh = hbase + lh;
    const float* rwp = r_weights + (size_t)b * 25 * HW + (size_t)gh * W_IMG + (wbase + lw);

    // smem addresses of this thread's 5 slots per stage
    uint32_t wslot[3];
#pragma unroll
    for (int s = 0; s < 3; s++)
        wslot[s] = (uint32_t)__cvta_generic_to_shared(&wbuf[s][0][ty][lw]);
    const uint32_t tap_stride = (uint32_t)(BY * TILE_W * sizeof(float));  // j -> j+1

    // ---- issue weight prefetch for di=0,1 immediately (overlaps everything below) ----
#pragma unroll
    for (int j = 0; j < 5; j++)
        cp_async8(wslot[0] + j * tap_stride, rwp + (size_t)j * HW);
    cp_commit();
#pragma unroll
    for (int j = 0; j < 5; j++)
        cp_async8(wslot[1] + j * tap_stride, rwp + (size_t)(5 + j) * HW);
    cp_commit();

    // ---- producer path: first NPROD blocks compute gray-max partials ----
    if (lbid < NPROD) {
        const int gb    = lbid / CH_PB;
        const int chunk = lbid - gb * CH_PB;
        const float4* p4 = reinterpret_cast<const float4*>(gray + (size_t)gb * HW);
        const int base = chunk * 2048;
        float m = 0.0f;
#pragma unroll
        for (int k = 0; k < 8; k++) {
            float4 v = p4[base + tid + k * 256];
            m = fmaxf(m, fmaxf(fmaxf(v.x, v.y), fmaxf(v.z, v.w)));
        }
#pragma unroll
        for (int o = 16; o > 0; o >>= 1)
            m = fmaxf(m, __shfl_down_sync(0xFFFFFFFFu, m, o));
        if ((tid & 31) == 0) redA[tid >> 5] = m;
        __syncthreads();
        if (tid == 0) {
            float mm = redA[0];
#pragma unroll
            for (int w = 1; w < BY; w++) mm = fmaxf(mm, redA[w]);
            g_gmax_partial[lbid] = mm;
            __threadfence();
            atomicAdd(&g_count, 1);
        }
        __syncthreads();   // redA reused later
    }

    const float ff   = f_factors[b];
    const float expo = 1.0f - ff;

    const float* fp = fake      + (size_t)b * HW;
    const float* gp = gamma_hdr + (size_t)b * HW;
    const float* hp = hdr_im    + (size_t)b * HW;

    // stage tile + halo (zero-pad OOB); hdr gets pow applied here
    for (int i = tid; i < SM_H * SM_W; i += NTHREADS) {
        const int r  = i / SM_W;
        const int c  = i - r * SM_W;
        const int ghh = hbase + r - HALO;
        const int gww = wbase + c - HALO;
        float vf = 0.0f, vg = 0.0f, vh = 0.0f;
        if (ghh >= 0 && ghh < H_IMG && gww >= 0 && gww < W_IMG) {
            const int gi = ghh * W_IMG + gww;
            vf = fp[gi];
            vg = gp[gi];
            vh = __powf(hp[gi], expo);
        }
        sf[i] = vf; sg[i] = vg; sh[i] = vh;
    }
    __syncthreads();

    float s1f[PPT] = {0,0}, s2f[PPT] = {0,0};
    float s1g[PPT] = {0,0}, s2g[PPT] = {0,0};
    float s1h[PPT] = {0,0}, ws [PPT] = {0,0};

#pragma unroll
    for (int di = 0; di < 5; di++) {
        // prefetch stage di+2 (2 iterations ahead)
        if (di + 2 < 5) {
            const uint32_t dslot = wslot[(di + 2) % 3];
#pragma unroll
            for (int j = 0; j < 5; j++)
                cp_async8(dslot + j * tap_stride, rwp + (size_t)((di + 2) * 5 + j) * HW);
            cp_commit();
        }
        // wait until stage di's group has landed (per-thread; we read only our own slots)
        if (di < 3)      asm volatile("cp.async.wait_group 2;" ::: "memory");
        else if (di == 3) asm volatile("cp.async.wait_group 1;" ::: "memory");
        else              asm volatile("cp.async.wait_group 0;" ::: "memory");

        const int buf = di % 3;
        float2 wv[5];
#pragma unroll
        for (int j = 0; j < 5; j++)
            wv[j] = *reinterpret_cast<const float2*>(&wbuf[buf][j][ty][lw]);

        const int rowoff = (lh + di) * SM_W + lw;
        const float2 f0 = *reinterpret_cast<const float2*>(&sf[rowoff]);
        const float2 f1 = *reinterpret_cast<const float2*>(&sf[rowoff + 2]);
        const float2 f2 = *reinterpret_cast<const float2*>(&sf[rowoff + 4]);
        const float2 g0 = *reinterpret_cast<const float2*>(&sg[rowoff]);
        const float2 g1 = *reinterpret_cast<const float2*>(&sg[rowoff + 2]);
        const float2 g2 = *reinterpret_cast<const float2*>(&sg[rowoff + 4]);
        const float2 h0 = *reinterpret_cast<const float2*>(&sh[rowoff]);
        const float2 h1 = *reinterpret_cast<const float2*>(&sh[rowoff + 2]);
        const float2 h2 = *reinterpret_cast<const float2*>(&sh[rowoff + 4]);
        const float xf[6] = {f0.x, f0.y, f1.x, f1.y, f2.x, f2.y};
        const float xg[6] = {g0.x, g0.y, g1.x, g1.y, g2.x, g2.y};
        const float xh[6] = {h0.x, h0.y, h1.x, h1.y, h2.x, h2.y};

#pragma unroll
        for (int dj = 0; dj < 5; dj++) {
            const float rwa[PPT] = {wv[dj].x, wv[dj].y};
#pragma unroll
            for (int l = 0; l < PPT; l++) {
                const float w = rwa[l];
                ws[l] += w;
                const float a = xf[dj + l];
                const float wa = w * a;
                s1f[l] += wa;
                s2f[l] = fmaf(wa, a, s2f[l]);
                const float gq = xg[dj + l];
                const float wg = w * gq;
                s1g[l] += wg;
                s2g[l] = fmaf(wg, gq, s2g[l]);
                s1h[l] = fmaf(w, xh[dj + l], s1h[l]);
            }
        }
    }

    // ---- wait for gray-max producers (long since done), reduce per-batch ----
    if (tid == 0) {
        while (*(volatile int*)&g_count < NPROD) { }
    }
    __syncthreads();
    __threadfence();
    if (tid < 32) {
        float m = g_gmax_partial[b * CH_PB + tid];
#pragma unroll
        for (int o = 16; o > 0; o >>= 1)
            m = fmaxf(m, __shfl_down_sync(0xFFFFFFFFu, m, o));
        if (tid == 0) s_gmax = m;
    }
    __syncthreads();
    const float cobj = s_gmax / ff;   // ALPHA = 1

    // ---- epilogue ----
    float accA = 0.0f, accB = 0.0f;
#pragma unroll
    for (int l = 0; l < PPT; l++) {
        const float inv  = 1.0f / ws[l];
        const float muf  = s1f[l] * inv;
        const float vrf  = fmaxf(s2f[l] * inv - muf * muf, 0.0f);
        const float stdf = sqrtf(vrf + EPS);
        const float mug  = s1g[l] * inv;
        const float vrg  = fmaxf(s2g[l] * inv - mug * mug, 0.0f);
        const float stdg = sqrtf(vrg + EPS);
        const float muh  = s1h[l] * inv;
        const float obj  = cobj * stdg * (muh + EPS);
        const float r    = 1.0f - stdf / (stdf + obj);
        const float wblf = ws[l] - 1.0f;
        accA = fmaf(r, wblf, accA);
        accB += wblf;
    }

    // block reduction -> per-block partials
#pragma unroll
    for (int o = 16; o > 0; o >>= 1) {
        accA += __shfl_down_sync(0xFFFFFFFFu, accA, o);
        accB += __shfl_down_sync(0xFFFFFFFFu, accB, o);
    }
    const int wid = tid >> 5, lane = tid & 31;
    if (lane == 0) { redA[wid] = accA; redB[wid] = accB; }
    __syncthreads();
    if (wid == 0) {
        accA = (lane < BY) ? redA[lane] : 0.0f;
        accB = (lane < BY) ? redB[lane] : 0.0f;
#pragma unroll
        for (int o = 4; o > 0; o >>= 1) {
            accA += __shfl_down_sync(0xFFFFFFFFu, accA, o);
            accB += __shfl_down_sync(0xFFFFFFFFu, accB, o);
        }
        if (lane == 0) {
            g_blockA[lbid] = accA;
            g_blockB[lbid] = accB;
        }
    }

    // ---- last-block-done election: single-kernel finalize ----
    __threadfence();
    if (tid == 0) s_last = atomicAdd(&g_done, 1);
    __syncthreads();
    if (s_last == NBLK_MAIN - 1) {
        float a = 0.0f, bsum = 0.0f;
        for (int i = tid; i < NBLK_MAIN; i += NTHREADS) {
            a    += g_blockA[i];
            bsum += g_blockB[i];
        }
#pragma unroll
        for (int o = 16; o > 0; o >>= 1) {
            a    += __shfl_down_sync(0xFFFFFFFFu, a, o);
            bsum += __shfl_down_sync(0xFFFFFFFFu, bsum, o);
        }
        if (lane == 0) { redA[wid] = a; redB[wid] = bsum; }
        __syncthreads();
        if (wid == 0) {
            a    = (lane < BY) ? redA[lane] : 0.0f;
            bsum = (lane < BY) ? redB[lane] : 0.0f;
#pragma unroll
            for (int o = 4; o > 0; o >>= 1) {
                a    += __shfl_down_sync(0xFFFFFFFFu, a, o);
                bsum += __shfl_down_sync(0xFFFFFFFFu, bsum, o);
            }
            if (lane == 0) {
                out[0] = a / bsum;
                g_done  = 0;
                g_count = 0;
            }
        }
    }
}

extern "C" void kernel_launch(void* const* d_in, const int* in_sizes, int n_in,
                              void* d_out, int out_size) {
    const float* fake      = (const float*)d_in[0];
    const float* gamma_hdr = (const float*)d_in[1];
    const float* hdr_im    = (const float*)d_in[2];
    const float* r_weights = (const float*)d_in[3];
    const float* f_factors = (const float*)d_in[4];
    const float* gray      = (const float*)d_in[5];
    float* out = (float*)d_out;

    dim3 grid(W_IMG / TILE_W, H_IMG / TILE_H, NB);
    dim3 block(BX, BY);
    intensity_loss_main<<<grid, block>>>(fake, gamma_hdr, hdr_im,
                                         r_weights, f_factors, gray, out);
}

// round 8
// speedup vs baseline: 1.0593x; 1.0593x over previous
#include <cuda_runtime.h>
#include <cstdint>

#define W_IMG 512
#define H_IMG 512
#define HW    (512*512)
#define NB    4
#define EPS   1e-5f

#define TILE_W 64
#define TILE_H 8
#define BX 32
#define BY 8
#define NTHREADS (BX*BY)
#define PPT 2
#define HALO 2
#define SM_W (TILE_W + 2*HALO)   // 68
#define SM_H (TILE_H + 2*HALO)   // 12

#define NPROD 128                 // gray-max producer blocks (wave-1 resident)
#define CH_PB (NPROD / NB)        // 32 chunks per batch
#define NBLK_MAIN (NB * (H_IMG/TILE_H) * (W_IMG/TILE_W))    // 2048

// scratch (no device allocs) — counters reset by the electing last block each replay
__device__ float g_gmax_partial[NPROD];
__device__ int   g_count;
__device__ int   g_done;
__device__ float g_blockA[NBLK_MAIN];
__device__ float g_blockB[NBLK_MAIN];

// ---- packed f32x2 helpers (sm_103a; ptxas never emits these from C++) ----
typedef unsigned long long u64;
__device__ __forceinline__ u64 pack2(float lo, float hi) {
    u64 d;
    asm("mov.b64 %0, {%1, %2};" : "=l"(d)
        : "r"(__float_as_uint(lo)), "r"(__float_as_uint(hi)));
    return d;
}
__device__ __forceinline__ void unpack2(u64 v, float& lo, float& hi) {
    unsigned int a, b;
    asm("mov.b64 {%0, %1}, %2;" : "=r"(a), "=r"(b) : "l"(v));
    lo = __uint_as_float(a); hi = __uint_as_float(b);
}
__device__ __forceinline__ u64 fma2(u64 a, u64 b, u64 c) {
    u64 d;
    asm("fma.rn.f32x2 %0, %1, %2, %3;" : "=l"(d) : "l"(a), "l"(b), "l"(c));
    return d;
}
__device__ __forceinline__ u64 mul2(u64 a, u64 b) {
    u64 d;
    asm("mul.rn.f32x2 %0, %1, %2;" : "=l"(d) : "l"(a), "l"(b));
    return d;
}
__device__ __forceinline__ u64 add2(u64 a, u64 b) {
    u64 d;
    asm("add.rn.f32x2 %0, %1, %2;" : "=l"(d) : "l"(a), "l"(b));
    return d;
}

__global__ __launch_bounds__(NTHREADS, 4)
void intensity_loss_main(const float* __restrict__ fake,
                         const float* __restrict__ gamma_hdr,
                         const float* __restrict__ hdr_im,
                         const float* __restrict__ r_weights,
                         const float* __restrict__ f_factors,
                         const float* __restrict__ gray,
                         float* __restrict__ out) {
    __shared__ __align__(16) float sf[SM_H * SM_W];
    __shared__ __align__(16) float sg[SM_H * SM_W];
    __shared__ __align__(16) float sh[SM_H * SM_W];
    __shared__ float redA[BY], redB[BY];
    __shared__ float s_gmax;
    __shared__ int   s_last;

    const int b     = blockIdx.z;
    const int wbase = blockIdx.x * TILE_W;
    const int hbase = blockIdx.y * TILE_H;
    const int tx    = threadIdx.x;
    const int ty    = threadIdx.y;
    const int tid   = ty * BX + tx;
    const int lbid  = blockIdx.x + (int)gridDim.x * (blockIdx.y + 64 * blockIdx.z);

    // ---- producer path: first NPROD blocks compute gray-max partials FIRST ----
    if (lbid < NPROD) {
        const int gb    = lbid / CH_PB;
        const int chunk = lbid - gb * CH_PB;
        const float4* p4 = reinterpret_cast<const float4*>(gray + (size_t)gb * HW);
        const int base = chunk * 2048;
        float m = 0.0f;
#pragma unroll
        for (int k = 0; k < 8; k++) {
            float4 v = p4[base + tid + k * 256];
            m = fmaxf(m, fmaxf(fmaxf(v.x, v.y), fmaxf(v.z, v.w)));
        }
#pragma unroll
        for (int o = 16; o > 0; o >>= 1)
            m = fmaxf(m, __shfl_down_sync(0xFFFFFFFFu, m, o));
        if ((tid & 31) == 0) redA[tid >> 5] = m;
        __syncthreads();
        if (tid == 0) {
            float mm = redA[0];
#pragma unroll
            for (int w = 1; w < BY; w++) mm = fmaxf(mm, redA[w]);
            g_gmax_partial[lbid] = mm;
            __threadfence();
            atomicAdd(&g_count, 1);
        }
        __syncthreads();   // redA reused later
    }

    const float ff   = f_factors[b];
    const float expo = 1.0f - ff;

    const float* fp = fake      + (size_t)b * HW;
    const float* gp = gamma_hdr + (size_t)b * HW;
    const float* hp = hdr_im    + (size_t)b * HW;

    // stage tile + halo (zero-pad OOB); hdr gets pow applied here
    for (int i = tid; i < SM_H * SM_W; i += NTHREADS) {
        const int r  = i / SM_W;
        const int c  = i - r * SM_W;
        const int ghh = hbase + r - HALO;
        const int gww = wbase + c - HALO;
        float vf = 0.0f, vg = 0.0f, vh = 0.0f;
        if (ghh >= 0 && ghh < H_IMG && gww >= 0 && gww < W_IMG) {
            const int gi = ghh * W_IMG + gww;
            vf = fp[gi];
            vg = gp[gi];
            vh = __powf(hp[gi], expo);
        }
        sf[i] = vf; sg[i] = vg; sh[i] = vh;
    }
    __syncthreads();

    const int lw = tx * PPT;   // even -> 8B-aligned shared reads
    const int lh = ty;
    const int gh = hbase + lh;
    const float* rwp = r_weights + (size_t)b * 25 * HW + (size_t)gh * W_IMG + (wbase + lw);

    // packed accumulators: lanes = (pixel0, pixel1)
    u64 s1f = 0, s2f = 0, s1g = 0, s2g = 0, s1h = 0, wsum = 0;

    // one tap: w = packed weight pair, P* = packed value pair (per-pixel window tap)
#define TAP(w, Pf, Pg, Ph)                 \
    do {                                   \
        wsum = add2(wsum, (w));            \
        const u64 wf = mul2((w), (Pf));    \
        s1f = add2(s1f, wf);               \
        s2f = fma2(wf, (Pf), s2f);         \
        const u64 wg = mul2((w), (Pg));    \
        s1g = add2(s1g, wg);               \
        s2g = fma2(wg, (Pg), s2g);         \
        s1h = fma2((w), (Ph), s1h);        \
    } while (0)

#pragma unroll
    for (int di = 0; di < 5; di++) {
        // 5 independent LDG.64; each IS the packed weight pair for (pixel0, pixel1)
        u64 wv[5];
#pragma unroll
        for (int j = 0; j < 5; j++)
            wv[j] = *reinterpret_cast<const u64*>(rwp + (size_t)(di * 5 + j) * HW);

        const int rowoff = (lh + di) * SM_W + lw;
        // aligned pairs: F0=(x0,x1) F1=(x2,x3) F2=(x4,x5) — free u64 views
        const float2 f0 = *reinterpret_cast<const float2*>(&sf[rowoff]);
        const float2 f1 = *reinterpret_cast<const float2*>(&sf[rowoff + 2]);
        const float2 f2 = *reinterpret_cast<const float2*>(&sf[rowoff + 4]);
        const float2 g0 = *reinterpret_cast<const float2*>(&sg[rowoff]);
        const float2 g1 = *reinterpret_cast<const float2*>(&sg[rowoff + 2]);
        const float2 g2 = *reinterpret_cast<const float2*>(&sg[rowoff + 4]);
        const float2 h0 = *reinterpret_cast<const float2*>(&sh[rowoff]);
        const float2 h1 = *reinterpret_cast<const float2*>(&sh[rowoff + 2]);
        const float2 h2 = *reinterpret_cast<const float2*>(&sh[rowoff + 4]);
        const u64 F0 = *reinterpret_cast<const u64*>(&f0);
        const u64 F1 = *reinterpret_cast<const u64*>(&f1);
        const u64 F2 = *reinterpret_cast<const u64*>(&f2);
        const u64 G0 = *reinterpret_cast<const u64*>(&g0);
        const u64 G1 = *reinterpret_cast<const u64*>(&g1);
        const u64 G2 = *reinterpret_cast<const u64*>(&g2);
        const u64 H0 = *reinterpret_cast<const u64*>(&h0);
        const u64 H1 = *reinterpret_cast<const u64*>(&h1);
        const u64 H2 = *reinterpret_cast<const u64*>(&h2);

        // even taps: aligned pairs, zero packing cost
        TAP(wv[0], F0, G0, H0);
        TAP(wv[2], F1, G1, H1);
        TAP(wv[4], F2, G2, H2);
        // odd taps: JIT mid-pairs (x1,x2) and (x3,x4) — 3 packs each, short-lived
        {
            const u64 Pf = pack2(f0.y, f1.x);
            const u64 Pg = pack2(g0.y, g1.x);
            const u64 Ph = pack2(h0.y, h1.x);
            TAP(wv[1], Pf, Pg, Ph);
        }
        {
            const u64 Pf = pack2(f1.y, f2.x);
            const u64 Pg = pack2(g1.y, g2.x);
            const u64 Ph = pack2(h1.y, h2.x);
            TAP(wv[3], Pf, Pg, Ph);
        }
    }
#undef TAP

    // ---- wait for gray-max producers (long since done), reduce per-batch ----
    if (tid == 0) {
        while (*(volatile int*)&g_count < NPROD) { }
    }
    __syncthreads();
    __threadfence();
    if (tid < 32) {
        float m = g_gmax_partial[b * CH_PB + tid];
#pragma unroll
        for (int o = 16; o > 0; o >>= 1)
            m = fmaxf(m, __shfl_down_sync(0xFFFFFFFFu, m, o));
        if (tid == 0) s_gmax = m;
    }
    __syncthreads();
    const float cobj = s_gmax / ff;   // ALPHA = 1

    // ---- epilogue: unpack, per-pixel scalar math ----
    float a1f[2], a2f[2], a1g[2], a2g[2], a1h[2], aws[2];
    unpack2(s1f,  a1f[0], a1f[1]);
    unpack2(s2f,  a2f[0], a2f[1]);
    unpack2(s1g,  a1g[0], a1g[1]);
    unpack2(s2g,  a2g[0], a2g[1]);
    unpack2(s1h,  a1h[0], a1h[1]);
    unpack2(wsum, aws[0], aws[1]);

    float accA = 0.0f, accB = 0.0f;
#pragma unroll
    for (int q = 0; q < 2; q++) {
        const float ws   = aws[q];
        const float inv  = 1.0f / ws;
        const float muf  = a1f[q] * inv;
        const float vrf  = fmaxf(a2f[q] * inv - muf * muf, 0.0f);
        const float stdf = sqrtf(vrf + EPS);
        const float mug  = a1g[q] * inv;
        const float vrg  = fmaxf(a2g[q] * inv - mug * mug, 0.0f);
        const float stdg = sqrtf(vrg + EPS);
        const float muh  = a1h[q] * inv;
        const float obj  = cobj * stdg * (muh + EPS);
        const float r    = 1.0f - stdf / (stdf + obj);
        const float wblf = ws - 1.0f;
        accA = fmaf(r, wblf, accA);
        accB += wblf;
    }

    // block reduction -> per-block partials
#pragma unroll
    for (int o = 16; o > 0; o >>= 1) {
        accA += __shfl_down_sync(0xFFFFFFFFu, accA, o);
        accB += __shfl_down_sync(0xFFFFFFFFu, accB, o);
    }
    const int wid = tid >> 5, lane = tid & 31;
    if (lane == 0) { redA[wid] = accA; redB[wid] = accB; }
    __syncthreads();
    if (wid == 0) {
        accA = (lane < BY) ? redA[lane] : 0.0f;
        accB = (lane < BY) ? redB[lane] : 0.0f;
#pragma unroll
        for (int o = 4; o > 0; o >>= 1) {
            accA += __shfl_down_sync(0xFFFFFFFFu, accA, o);
            accB += __shfl_down_sync(0xFFFFFFFFu, accB, o);
        }
        if (lane == 0) {
            g_blockA[lbid] = accA;
            g_blockB[lbid] = accB;
        }
    }

    // ---- last-block-done election: single-kernel finalize ----
    __threadfence();
    if (tid == 0) s_last = atomicAdd(&g_done, 1);
    __syncthreads();
    if (s_last == NBLK_MAIN - 1) {
        float a = 0.0f, bsum = 0.0f;
        for (int i = tid; i < NBLK_MAIN; i += NTHREADS) {
            a    += g_blockA[i];
            bsum += g_blockB[i];
        }
#pragma unroll
        for (int o = 16; o > 0; o >>= 1) {
            a    += __shfl_down_sync(0xFFFFFFFFu, a, o);
            bsum += __shfl_down_sync(0xFFFFFFFFu, bsum, o);
        }
        if (lane == 0) { redA[wid] = a; redB[wid] = bsum; }
        __syncthreads();
        if (wid == 0) {
            a    = (lane < BY) ? redA[lane] : 0.0f;
            bsum = (lane < BY) ? redB[lane] : 0.0f;
#pragma unroll
            for (int o = 4; o > 0; o >>= 1) {
                a    += __shfl_down_sync(0xFFFFFFFFu, a, o);
                bsum += __shfl_down_sync(0xFFFFFFFFu, bsum, o);
            }
            if (lane == 0) {
                out[0] = a / bsum;
                g_done  = 0;
                g_count = 0;
            }
        }
    }
}

extern "C" void kernel_launch(void* const* d_in, const int* in_sizes, int n_in,
                              void* d_out, int out_size) {
    const float* fake      = (const float*)d_in[0];
    const float* gamma_hdr = (const float*)d_in[1];
    const float* hdr_im    = (const float*)d_in[2];
    const float* r_weights = (const float*)d_in[3];
    const float* f_factors = (const float*)d_in[4];
    const float* gray      = (const float*)d_in[5];
    float* out = (float*)d_out;

    dim3 grid(W_IMG / TILE_W, H_IMG / TILE_H, NB);
    dim3 block(BX, BY);
    intensity_loss_main<<<grid, block>>>(fake, gamma_hdr, hdr_im,
                                         r_weights, f_factors, gray, out);
}

// round 9
// speedup vs baseline: 1.0601x; 1.0008x over previous
#include <cuda_runtime.h>
#include <cstdint>

#define W_IMG 512
#define H_IMG 512
#define HW    (512*512)
#define NB    4
#define EPS   1e-5f

#define TILE_W 128
#define TILE_H 8
#define BX 32
#define BY 8
#define NTHREADS (BX*BY)
#define PPT 4
#define HALO 2
#define SM_W (TILE_W + 2*HALO)   // 132
#define SM_H (TILE_H + 2*HALO)   // 12

#define NPROD 128                 // gray-max producer blocks (wave-1 resident: 128 < 444 conc)
#define CH_PB (NPROD / NB)        // 32 chunks per batch
#define NBLK_MAIN (NB * (H_IMG/TILE_H) * (W_IMG/TILE_W))    // 4*64*4 = 1024

// scratch (no device allocs) — counters reset by the electing last block each replay
__device__ float g_gmax_partial[NPROD];
__device__ int   g_count;
__device__ int   g_done;
__device__ float g_blockA[NBLK_MAIN];
__device__ float g_blockB[NBLK_MAIN];

__global__ __launch_bounds__(NTHREADS, 3)
void intensity_loss_main(const float* __restrict__ fake,
                         const float* __restrict__ gamma_hdr,
                         const float* __restrict__ hdr_im,
                         const float* __restrict__ r_weights,
                         const float* __restrict__ f_factors,
                         const float* __restrict__ gray,
                         float* __restrict__ out) {
    __shared__ __align__(16) float sf[SM_H * SM_W];
    __shared__ __align__(16) float sg[SM_H * SM_W];
    __shared__ __align__(16) float sh[SM_H * SM_W];
    __shared__ float redA[BY], redB[BY];
    __shared__ float s_gmax;
    __shared__ int   s_last;

    const int b     = blockIdx.z;
    const int wbase = blockIdx.x * TILE_W;
    const int hbase = blockIdx.y * TILE_H;
    const int tx    = threadIdx.x;
    const int ty    = threadIdx.y;
    const int tid   = ty * BX + tx;
    const int lbid  = blockIdx.x + 4 * (blockIdx.y + 64 * blockIdx.z);

    // ---- producer path: first NPROD blocks compute gray-max partials FIRST ----
    if (lbid < NPROD) {
        const int gb    = lbid / CH_PB;
        const int chunk = lbid - gb * CH_PB;
        const float4* p4 = reinterpret_cast<const float4*>(gray + (size_t)gb * HW);
        const int base = chunk * 2048;
        float m = 0.0f;
#pragma unroll
        for (int k = 0; k < 8; k++) {
            float4 v = p4[base + tid + k * 256];
            m = fmaxf(m, fmaxf(fmaxf(v.x, v.y), fmaxf(v.z, v.w)));
        }
#pragma unroll
        for (int o = 16; o > 0; o >>= 1)
            m = fmaxf(m, __shfl_down_sync(0xFFFFFFFFu, m, o));
        if ((tid & 31) == 0) redA[tid >> 5] = m;
        __syncthreads();
        if (tid == 0) {
            float mm = redA[0];
#pragma unroll
            for (int w = 1; w < BY; w++) mm = fmaxf(mm, redA[w]);
            g_gmax_partial[lbid] = mm;
            __threadfence();
            atomicAdd(&g_count, 1);
        }
        __syncthreads();   // redA reused later
    }

    const float ff   = f_factors[b];
    const float expo = 1.0f - ff;

    const float* fp = fake      + (size_t)b * HW;
    const float* gp = gamma_hdr + (size_t)b * HW;
    const float* hp = hdr_im    + (size_t)b * HW;

    // stage tile + halo (zero-pad OOB); hdr gets pow applied here
    for (int i = tid; i < SM_H * SM_W; i += NTHREADS) {
        const int r  = i / SM_W;
        const int c  = i - r * SM_W;
        const int ghh = hbase + r - HALO;
        const int gww = wbase + c - HALO;
        float vf = 0.0f, vg = 0.0f, vh = 0.0f;
        if (ghh >= 0 && ghh < H_IMG && gww >= 0 && gww < W_IMG) {
            const int gi = ghh * W_IMG + gww;
            vf = fp[gi];
            vg = gp[gi];
            vh = __powf(hp[gi], expo);
        }
        sf[i] = vf; sg[i] = vg; sh[i] = vh;
    }
    __syncthreads();

    const int lw = tx * PPT;      // multiple of 4 -> 16B-aligned shared reads
    const int lh = ty;
    const int gh = hbase + lh;
    const float* rwp = r_weights + (size_t)b * 25 * HW + (size_t)gh * W_IMG + (wbase + lw);

    float s1f[PPT] = {0,0,0,0}, s2f[PPT] = {0,0,0,0};
    float s1g[PPT] = {0,0,0,0}, s2g[PPT] = {0,0,0,0};
    float s1h[PPT] = {0,0,0,0}, ws [PPT] = {0,0,0,0};

#pragma unroll
    for (int di = 0; di < 5; di++) {
        // 5 independent LDG.128 (2048B in flight per warp); inner offsets are
        // <=4MB immediates, di handled by pointer bump below (1 IADD.64/iter)
        float4 wv[5];
#pragma unroll
        for (int j = 0; j < 5; j++)
            wv[j] = *reinterpret_cast<const float4*>(rwp + (size_t)j * HW);

        const int rowoff = (lh + di) * SM_W + lw;   // 16B-aligned
        const float4 f0 = *reinterpret_cast<const float4*>(&sf[rowoff]);
        const float4 f1 = *reinterpret_cast<const float4*>(&sf[rowoff + 4]);
        const float4 g0 = *reinterpret_cast<const float4*>(&sg[rowoff]);
        const float4 g1 = *reinterpret_cast<const float4*>(&sg[rowoff + 4]);
        const float4 h0 = *reinterpret_cast<const float4*>(&sh[rowoff]);
        const float4 h1 = *reinterpret_cast<const float4*>(&sh[rowoff + 4]);
        const float xf[8] = {f0.x, f0.y, f0.z, f0.w, f1.x, f1.y, f1.z, f1.w};
        const float xg[8] = {g0.x, g0.y, g0.z, g0.w, g1.x, g1.y, g1.z, g1.w};
        const float xh[8] = {h0.x, h0.y, h0.z, h0.w, h1.x, h1.y, h1.z, h1.w};

#pragma unroll
        for (int dj = 0; dj < 5; dj++) {
            const float rwa[PPT] = {wv[dj].x, wv[dj].y, wv[dj].z, wv[dj].w};
#pragma unroll
            for (int l = 0; l < PPT; l++) {
                const float w = rwa[l];
                ws[l] += w;
                const float a = xf[dj + l];
                const float wa = w * a;
                s1f[l] += wa;
                s2f[l] = fmaf(wa, a, s2f[l]);
                const float gq = xg[dj + l];
                const float wg = w * gq;
                s1g[l] += wg;
                s2g[l] = fmaf(wg, gq, s2g[l]);
                s1h[l] = fmaf(w, xh[dj + l], s1h[l]);
            }
        }
        rwp += (size_t)5 * HW;   // pointer bump: next tap row
    }

    // ---- wait for gray-max producers (long since done), reduce per-batch ----
    if (tid == 0) {
        while (*(volatile int*)&g_count < NPROD) { }
    }
    __syncthreads();
    __threadfence();
    if (tid < 32) {
        float m = g_gmax_partial[b * CH_PB + tid];
#pragma unroll
        for (int o = 16; o > 0; o >>= 1)
            m = fmaxf(m, __shfl_down_sync(0xFFFFFFFFu, m, o));
        if (tid == 0) s_gmax = m;
    }
    __syncthreads();
    const float cobj = s_gmax / ff;   // ALPHA = 1

    // ---- epilogue: per-pixel scalar math ----
    float accA = 0.0f, accB = 0.0f;
#pragma unroll
    for (int l = 0; l < PPT; l++) {
        const float wsl  = ws[l];
        const float inv  = 1.0f / wsl;
        const float muf  = s1f[l] * inv;
        const float vrf  = fmaxf(s2f[l] * inv - muf * muf, 0.0f);
        const float stdf = sqrtf(vrf + EPS);
        const float mug  = s1g[l] * inv;
        const float vrg  = fmaxf(s2g[l] * inv - mug * mug, 0.0f);
        const float stdg = sqrtf(vrg + EPS);
        const float muh  = s1h[l] * inv;
        const float obj  = cobj * stdg * (muh + EPS);
        const float r    = 1.0f - stdf / (stdf + obj);
        const float wblf = wsl - 1.0f;
        accA = fmaf(r, wblf, accA);
        accB += wblf;
    }

    // block reduction -> per-block partials
#pragma unroll
    for (int o = 16; o > 0; o >>= 1) {
        accA += __shfl_down_sync(0xFFFFFFFFu, accA, o);
        accB += __shfl_down_sync(0xFFFFFFFFu, accB, o);
    }
    const int wid = tid >> 5, lane = tid & 31;
    if (lane == 0) { redA[wid] = accA; redB[wid] = accB; }
    __syncthreads();
    if (wid == 0) {
        accA = (lane < BY) ? redA[lane] : 0.0f;
        accB = (lane < BY) ? redB[lane] : 0.0f;
#pragma unroll
        for (int o = 4; o > 0; o >>= 1) {
            accA += __shfl_down_sync(0xFFFFFFFFu, accA, o);
            accB += __shfl_down_sync(0xFFFFFFFFu, accB, o);
        }
        if (lane == 0) {
            g_blockA[lbid] = accA;
            g_blockB[lbid] = accB;
        }
    }

    // ---- last-block-done election: single-kernel finalize ----
    __threadfence();
    if (tid == 0) s_last = atomicAdd(&g_done, 1);
    __syncthreads();
    if (s_last == NBLK_MAIN - 1) {
        float a = 0.0f, bsum = 0.0f;
#pragma unroll
        for (int k = 0; k < NBLK_MAIN / NTHREADS; k++) {
            a    += g_blockA[tid + k * NTHREADS];
            bsum += g_blockB[tid + k * NTHREADS];
        }
#pragma unroll
        for (int o = 16; o > 0; o >>= 1) {
            a    += __shfl_down_sync(0xFFFFFFFFu, a, o);
            bsum += __shfl_down_sync(0xFFFFFFFFu, bsum, o);
        }
        if (lane == 0) { redA[wid] = a; redB[wid] = bsum; }
        __syncthreads();
        if (wid == 0) {
            a    = (lane < BY) ? redA[lane] : 0.0f;
            bsum = (lane < BY) ? redB[lane] : 0.0f;
#pragma unroll
            for (int o = 4; o > 0; o >>= 1) {
                a    += __shfl_down_sync(0xFFFFFFFFu, a, o);
                bsum += __shfl_down_sync(0xFFFFFFFFu, bsum, o);
            }
            if (lane == 0) {
                out[0] = a / bsum;
                g_done  = 0;
                g_count = 0;
            }
        }
    }
}

extern "C" void kernel_launch(void* const* d_in, const int* in_sizes, int n_in,
                              void* d_out, int out_size) {
    const float* fake      = (const float*)d_in[0];
    const float* gamma_hdr = (const float*)d_in[1];
    const float* hdr_im    = (const float*)d_in[2];
    const float* r_weights = (const float*)d_in[3];
    const float* f_factors = (const float*)d_in[4];
    const float* gray      = (const float*)d_in[5];
    float* out = (float*)d_out;

    dim3 grid(W_IMG / TILE_W, H_IMG / TILE_H, NB);
    dim3 block(BX, BY);
    intensity_loss_main<<<grid, block>>>(fake, gamma_hdr, hdr_im,
                                         r_weights, f_factors, gray, out);
}